// round 2
// baseline (speedup 1.0000x reference)
#include <cuda_runtime.h>
#include <cuda_bf16.h>
#include <cstdint>
#include <math.h>

// Problem constants
#define PLANE   (2048*2048)       // 4,194,304 pixels per channel plane
#define NBINS   4913              // 17^3 distinct compact keys (289a+17b+c)
#define NFEAT   20

#define K1_BLOCKS  148
#define K1_THREADS 1024
#define K2_THREADS 256
#define K2_BLOCKS  ((NBINS + K2_THREADS - 1) / K2_THREADS)   // 20

// Scratch (no device allocation allowed -> __device__ globals).
// g_part: per-block histograms, layout [tensor(2)][block(148)][bin(4913)].
// Fully overwritten every launch -> deterministic, no zeroing pass needed.
__device__ unsigned int g_part[2 * K1_BLOCKS * NBINS];
__device__ int          g_bsums[K2_BLOCKS][NFEAT];

// ---------------------------------------------------------------------------
// Kernel 1: joint histogram of compact keys for x_in and x_s.
// Each block: shared 2x4913 uint32 histograms, shared atomics, flush to global.
// ---------------------------------------------------------------------------
__global__ void __launch_bounds__(K1_THREADS, 1)
hist_kernel(const float* __restrict__ x_in, const float* __restrict__ x_s)
{
    __shared__ unsigned int hm[NBINS];
    __shared__ unsigned int hl[NBINS];

    const int tid = threadIdx.x;
    for (int k = tid; k < NBINS; k += K1_THREADS) { hm[k] = 0u; hl[k] = 0u; }
    __syncthreads();

    const float4* __restrict__ a0 = (const float4*)(x_in);
    const float4* __restrict__ a1 = (const float4*)(x_in + PLANE);
    const float4* __restrict__ a2 = (const float4*)(x_in + 2 * PLANE);
    const float4* __restrict__ b0 = (const float4*)(x_s);
    const float4* __restrict__ b1 = (const float4*)(x_s + PLANE);
    const float4* __restrict__ b2 = (const float4*)(x_s + 2 * PLANE);

    const int N4     = PLANE / 4;                 // 1,048,576 float4 positions
    const int stride = K1_BLOCKS * K1_THREADS;

    for (int i = blockIdx.x * K1_THREADS + tid; i < N4; i += stride) {
        // Streaming loads: inputs are read exactly once, don't pollute L2.
        float4 va = __ldcs(&a0[i]);
        float4 vb = __ldcs(&a1[i]);
        float4 vc = __ldcs(&a2[i]);
        float4 wa = __ldcs(&b0[i]);
        float4 wb = __ldcs(&b1[i]);
        float4 wc = __ldcs(&b2[i]);

        // key = 289*a + 17*b + c  (exact in fp32: max 4912 < 2^24)
        int m0 = (int)fmaf(289.f, va.x, fmaf(17.f, vb.x, vc.x));
        int m1 = (int)fmaf(289.f, va.y, fmaf(17.f, vb.y, vc.y));
        int m2 = (int)fmaf(289.f, va.z, fmaf(17.f, vb.z, vc.z));
        int m3 = (int)fmaf(289.f, va.w, fmaf(17.f, vb.w, vc.w));
        int l0 = (int)fmaf(289.f, wa.x, fmaf(17.f, wb.x, wc.x));
        int l1 = (int)fmaf(289.f, wa.y, fmaf(17.f, wb.y, wc.y));
        int l2 = (int)fmaf(289.f, wa.z, fmaf(17.f, wb.z, wc.z));
        int l3 = (int)fmaf(289.f, wa.w, fmaf(17.f, wb.w, wc.w));

        atomicAdd(&hm[m0], 1u);
        atomicAdd(&hm[m1], 1u);
        atomicAdd(&hm[m2], 1u);
        atomicAdd(&hm[m3], 1u);
        atomicAdd(&hl[l0], 1u);
        atomicAdd(&hl[l1], 1u);
        atomicAdd(&hl[l2], 1u);
        atomicAdd(&hl[l3], 1u);
    }
    __syncthreads();

    // Flush: coalesced stores, layout [tensor][block][bin]
    unsigned int* __restrict__ pm = g_part + (size_t)blockIdx.x * NBINS;
    unsigned int* __restrict__ pl = g_part + (size_t)(K1_BLOCKS + blockIdx.x) * NBINS;
    for (int k = tid; k < NBINS; k += K1_THREADS) {
        pm[k] = hm[k];
        pl[k] = hl[k];
    }
}

// ---------------------------------------------------------------------------
// LUT dtype sniffer. The reference declares int8 tables, but the harness's
// supported dtype set is {float32, int32, bfloat16}; int8 is likely upcast.
// Classify from the first 256 32-bit words (deterministic; same result in
// every block). Values are integers in [-32, 31]:
//   int32  : every word in [-32, 31]        (other encodings: P ~ 0)
//   float32: every word, as float, is finite, integral, |v| <= 32
//   bf16   : both 16-bit halves decode to finite integral |v| <= 32
//   else   : raw int8 bytes
// ---------------------------------------------------------------------------
#define MODE_INT8   0
#define MODE_INT32  1
#define MODE_FP32   2
#define MODE_BF16   3

__device__ int detect_mode(const int* __restrict__ w)
{
    bool small = true, flt = true, bfl = true;
    for (int i = 0; i < 256; i++) {
        int v = w[i];
        if (v < -32 || v > 31) small = false;

        float f = __int_as_float(v);
        if (!(isfinite(f) && f == truncf(f) && fabsf(f) <= 32.f)) flt = false;

        unsigned u = (unsigned)v;
        float h0 = __bfloat162float(__ushort_as_bfloat16((unsigned short)(u & 0xFFFFu)));
        float h1 = __bfloat162float(__ushort_as_bfloat16((unsigned short)(u >> 16)));
        if (!(isfinite(h0) && h0 == truncf(h0) && fabsf(h0) <= 32.f &&
              isfinite(h1) && h1 == truncf(h1) && fabsf(h1) <= 32.f)) bfl = false;
    }
    if (small) return MODE_INT32;
    if (flt)   return MODE_FP32;
    if (bfl)   return MODE_BF16;
    return MODE_INT8;
}

__device__ __forceinline__ int fetch_lut(const void* __restrict__ tab, int mode, long long e)
{
    switch (mode) {
        case MODE_INT32: return ((const int*)tab)[e];
        case MODE_FP32:  return (int)((const float*)tab)[e];
        case MODE_BF16:  return (int)__bfloat162float(((const __nv_bfloat16*)tab)[e]);
        default:         return (int)((const signed char*)tab)[e];
    }
}

// ---------------------------------------------------------------------------
// Kernel 2: for each bin j, total counts across blocks, then weighted MAC
// with LUT rows msb[16j][0..19], lsb[16j][0..19]. Per-block partial sums.
// All sums fit int32 (|S| <= 4.2M * 64 ~= 2.7e8 < 2^31).
// ---------------------------------------------------------------------------
__global__ void __launch_bounds__(K2_THREADS)
reduce_kernel(const void* __restrict__ msb, const void* __restrict__ lsb)
{
    __shared__ int red[NFEAT];
    __shared__ int s_mode;
    const int tid = threadIdx.x;
    if (tid < NFEAT) red[tid] = 0;
    if (tid == 0) s_mode = detect_mode((const int*)msb);
    __syncthreads();
    const int mode = s_mode;

    const int j = blockIdx.x * K2_THREADS + tid;
    if (j < NBINS) {
        // Sum per-block partial counts (coalesced: consecutive j -> consecutive words)
        int cm = 0, cl = 0;
        #pragma unroll 4
        for (int b = 0; b < K1_BLOCKS; b++) {
            cm += (int)g_part[(size_t)b * NBINS + j];
            cl += (int)g_part[(size_t)(K1_BLOCKS + b) * NBINS + j];
        }
        // LUT row: original index = 16*j, element offset = 16*j*20 = 320*j
        const long long base = 320LL * j;
        #pragma unroll
        for (int f = 0; f < NFEAT; f++) {
            int v = cm * fetch_lut(msb, mode, base + f)
                  + cl * fetch_lut(lsb, mode, base + f);
            atomicAdd(&red[f], v);
        }
    }
    __syncthreads();
    if (tid < NFEAT) g_bsums[blockIdx.x][tid] = red[tid];
}

// ---------------------------------------------------------------------------
// Kernel 3: final mean + quantize.
// out = clip(round(mean*4)/4, -32, 31.75)
//     = clamp(rint(S / 2^20), -128, 127) * 0.25   (S integer; exact in double)
// rint = round-half-to-even, matching jnp.round.
// ---------------------------------------------------------------------------
__global__ void final_kernel(float* __restrict__ out)
{
    const int f = threadIdx.x;
    if (f < NFEAT) {
        long long s = 0;
        #pragma unroll
        for (int b = 0; b < K2_BLOCKS; b++) s += (long long)g_bsums[b][f];
        double q = rint((double)s / 1048576.0);   // S * 4 / 4194304
        q = fmin(fmax(q, -128.0), 127.0);
        out[f] = (float)(q * 0.25);
    }
}

// ---------------------------------------------------------------------------
extern "C" void kernel_launch(void* const* d_in, const int* in_sizes, int n_in,
                              void* d_out, int out_size)
{
    const float* x_in = (const float*)d_in[0];
    const float* x_s  = (const float*)d_in[1];
    const void*  msb  = d_in[2];
    const void*  lsb  = d_in[3];
    float*       out  = (float*)d_out;

    hist_kernel<<<K1_BLOCKS, K1_THREADS>>>(x_in, x_s);
    reduce_kernel<<<K2_BLOCKS, K2_THREADS>>>(msb, lsb);
    final_kernel<<<1, 32>>>(out);
}

// round 3
// speedup vs baseline: 1.6198x; 1.6198x over previous
#include <cuda_runtime.h>
#include <cuda_bf16.h>
#include <cstdint>
#include <math.h>

// Problem constants
#define PLANE   (2048*2048)       // 4,194,304 pixels per channel plane
#define NBINS   4913              // 17^3 distinct compact keys (289a+17b+c)
#define NFEAT   20

#define K1_BLOCKS  148
#define K1_THREADS 1024
#define K2_BLOCKS  20
#define K2_THREADS 256

// ---------------------------------------------------------------------------
// Global scratch. CUDA guarantees __device__ globals are zero at module load.
// Invariant maintained across launches (incl. graph replays): g_hist, g_accum
// and g_ticket are ZERO on entry to kernel_launch — the reduce kernel zeroes
// everything it consumed before finishing. Deterministic: integer sums,
// order-independent.
// ---------------------------------------------------------------------------
__device__ unsigned int g_hist[2 * NBINS];   // [msb bins | lsb bins]
__device__ int          g_accum[NFEAT];
__device__ unsigned int g_ticket;

// ---------------------------------------------------------------------------
// Kernel 1: joint histogram of compact keys for x_in and x_s.
// Shared 2x4913 uint32 histograms; 2x-unrolled streaming reads to raise MLP;
// flush via global atomicAdd into g_hist (assumed zero at entry).
// ---------------------------------------------------------------------------
__global__ void __launch_bounds__(K1_THREADS, 1)
hist_kernel(const float* __restrict__ x_in, const float* __restrict__ x_s)
{
    __shared__ unsigned int hm[NBINS];
    __shared__ unsigned int hl[NBINS];

    const int tid = threadIdx.x;
    for (int k = tid; k < NBINS; k += K1_THREADS) { hm[k] = 0u; hl[k] = 0u; }
    __syncthreads();

    const float4* __restrict__ a0 = (const float4*)(x_in);
    const float4* __restrict__ a1 = (const float4*)(x_in + PLANE);
    const float4* __restrict__ a2 = (const float4*)(x_in + 2 * PLANE);
    const float4* __restrict__ b0 = (const float4*)(x_s);
    const float4* __restrict__ b1 = (const float4*)(x_s + PLANE);
    const float4* __restrict__ b2 = (const float4*)(x_s + 2 * PLANE);

    const int NP     = PLANE / 8;                // pairs of float4 positions
    const int stride = K1_BLOCKS * K1_THREADS;

    for (int p = blockIdx.x * K1_THREADS + tid; p < NP; p += stride) {
        const int i0 = 2 * p, i1 = 2 * p + 1;
        // 12 independent streaming loads in flight per thread.
        float4 va0 = __ldcs(&a0[i0]); float4 va1 = __ldcs(&a0[i1]);
        float4 vb0 = __ldcs(&a1[i0]); float4 vb1 = __ldcs(&a1[i1]);
        float4 vc0 = __ldcs(&a2[i0]); float4 vc1 = __ldcs(&a2[i1]);
        float4 wa0 = __ldcs(&b0[i0]); float4 wa1 = __ldcs(&b0[i1]);
        float4 wb0 = __ldcs(&b1[i0]); float4 wb1 = __ldcs(&b1[i1]);
        float4 wc0 = __ldcs(&b2[i0]); float4 wc1 = __ldcs(&b2[i1]);

        // key = 289*a + 17*b + c  (exact in fp32: max 4912 < 2^24)
        atomicAdd(&hm[(int)fmaf(289.f, va0.x, fmaf(17.f, vb0.x, vc0.x))], 1u);
        atomicAdd(&hm[(int)fmaf(289.f, va0.y, fmaf(17.f, vb0.y, vc0.y))], 1u);
        atomicAdd(&hm[(int)fmaf(289.f, va0.z, fmaf(17.f, vb0.z, vc0.z))], 1u);
        atomicAdd(&hm[(int)fmaf(289.f, va0.w, fmaf(17.f, vb0.w, vc0.w))], 1u);
        atomicAdd(&hm[(int)fmaf(289.f, va1.x, fmaf(17.f, vb1.x, vc1.x))], 1u);
        atomicAdd(&hm[(int)fmaf(289.f, va1.y, fmaf(17.f, vb1.y, vc1.y))], 1u);
        atomicAdd(&hm[(int)fmaf(289.f, va1.z, fmaf(17.f, vb1.z, vc1.z))], 1u);
        atomicAdd(&hm[(int)fmaf(289.f, va1.w, fmaf(17.f, vb1.w, vc1.w))], 1u);

        atomicAdd(&hl[(int)fmaf(289.f, wa0.x, fmaf(17.f, wb0.x, wc0.x))], 1u);
        atomicAdd(&hl[(int)fmaf(289.f, wa0.y, fmaf(17.f, wb0.y, wc0.y))], 1u);
        atomicAdd(&hl[(int)fmaf(289.f, wa0.z, fmaf(17.f, wb0.z, wc0.z))], 1u);
        atomicAdd(&hl[(int)fmaf(289.f, wa0.w, fmaf(17.f, wb0.w, wc0.w))], 1u);
        atomicAdd(&hl[(int)fmaf(289.f, wa1.x, fmaf(17.f, wb1.x, wc1.x))], 1u);
        atomicAdd(&hl[(int)fmaf(289.f, wa1.y, fmaf(17.f, wb1.y, wc1.y))], 1u);
        atomicAdd(&hl[(int)fmaf(289.f, wa1.z, fmaf(17.f, wb1.z, wc1.z))], 1u);
        atomicAdd(&hl[(int)fmaf(289.f, wa1.w, fmaf(17.f, wb1.w, wc1.w))], 1u);
    }
    __syncthreads();

    // Flush into single global histogram (REDG, spread addresses).
    for (int k = tid; k < NBINS; k += K1_THREADS) {
        unsigned int vm = hm[k], vl = hl[k];
        if (vm) atomicAdd(&g_hist[k], vm);
        if (vl) atomicAdd(&g_hist[NBINS + k], vl);
    }
}

// ---------------------------------------------------------------------------
// LUT dtype sniffer (harness may upcast the declared int8 tables).
// Warp-parallel over the first 256 words; all blocks reach the same answer.
// ---------------------------------------------------------------------------
#define MODE_INT8   0
#define MODE_INT32  1
#define MODE_FP32   2
#define MODE_BF16   3

__device__ int detect_mode_warp(const int* __restrict__ w, int lane)
{
    bool small = true, flt = true, bfl = true;
    for (int i = lane; i < 256; i += 32) {
        int v = w[i];
        if (v < -32 || v > 31) small = false;

        float f = __int_as_float(v);
        if (!(isfinite(f) && f == truncf(f) && fabsf(f) <= 32.f)) flt = false;

        unsigned u = (unsigned)v;
        float h0 = __bfloat162float(__ushort_as_bfloat16((unsigned short)(u & 0xFFFFu)));
        float h1 = __bfloat162float(__ushort_as_bfloat16((unsigned short)(u >> 16)));
        if (!(isfinite(h0) && h0 == truncf(h0) && fabsf(h0) <= 32.f &&
              isfinite(h1) && h1 == truncf(h1) && fabsf(h1) <= 32.f)) bfl = false;
    }
    if (__all_sync(0xffffffffu, small)) return MODE_INT32;
    if (__all_sync(0xffffffffu, flt))   return MODE_FP32;
    if (__all_sync(0xffffffffu, bfl))   return MODE_BF16;
    return MODE_INT8;
}

__device__ __forceinline__ int fetch_lut(const void* __restrict__ tab, int mode, long long e)
{
    switch (mode) {
        case MODE_INT32: return ((const int*)tab)[e];
        case MODE_FP32:  return (int)((const float*)tab)[e];
        case MODE_BF16:  return (int)__bfloat162float(((const __nv_bfloat16*)tab)[e]);
        default:         return (int)((const signed char*)tab)[e];
    }
}

// ---------------------------------------------------------------------------
// Kernel 2 (fused reduce+final): per-bin weighted MAC with LUT rows, block
// partials into g_accum via atomics, last block (ticket) writes the output.
// Consumed state (g_hist, g_accum, g_ticket) is re-zeroed for the next launch.
// All sums fit int32 (|S| <= 2 * 4.2M * 32 ~= 2.7e8 < 2^31).
// ---------------------------------------------------------------------------
__global__ void __launch_bounds__(K2_THREADS)
reduce_final_kernel(const void* __restrict__ msb, const void* __restrict__ lsb,
                    float* __restrict__ out)
{
    __shared__ int red[NFEAT];
    __shared__ int s_mode;
    __shared__ int s_last;
    const int tid  = threadIdx.x;
    const int wid  = tid >> 5;
    const int lane = tid & 31;

    if (tid < NFEAT) red[tid] = 0;
    if (wid == 0) {
        int m = detect_mode_warp((const int*)msb, lane);
        if (lane == 0) s_mode = m;
    }
    __syncthreads();
    const int mode = s_mode;

    const int j = blockIdx.x * K2_THREADS + tid;
    if (j < NBINS) {
        int cm = (int)g_hist[j];
        int cl = (int)g_hist[NBINS + j];
        // zero-on-consume: restore invariant for next launch
        g_hist[j] = 0u;
        g_hist[NBINS + j] = 0u;

        if (cm | cl) {
            // LUT row: original index = 16*j, element offset = 16*j*20 = 320*j
            const long long base = 320LL * j;
            #pragma unroll
            for (int f = 0; f < NFEAT; f++) {
                int v = cm * fetch_lut(msb, mode, base + f)
                      + cl * fetch_lut(lsb, mode, base + f);
                atomicAdd(&red[f], v);
            }
        }
    }
    __syncthreads();

    if (tid < NFEAT) atomicAdd(&g_accum[tid], red[tid]);
    __threadfence();
    __syncthreads();

    if (tid == 0) {
        unsigned int t = atomicAdd(&g_ticket, 1u);
        s_last = (t == K2_BLOCKS - 1) ? 1 : 0;
    }
    __syncthreads();

    if (s_last && tid < NFEAT) {
        // Coherent read (L2 atomic), then reset for next launch.
        int S = atomicAdd(&g_accum[tid], 0);
        g_accum[tid] = 0;
        if (tid == 0) g_ticket = 0u;
        // out = clip(round(mean*4)/4, -32, 31.75)
        //     = clamp(rint(S / 2^20), -128, 127) * 0.25   (exact in double)
        double q = rint((double)S / 1048576.0);
        q = fmin(fmax(q, -128.0), 127.0);
        out[tid] = (float)(q * 0.25);
    }
}

// ---------------------------------------------------------------------------
extern "C" void kernel_launch(void* const* d_in, const int* in_sizes, int n_in,
                              void* d_out, int out_size)
{
    const float* x_in = (const float*)d_in[0];
    const float* x_s  = (const float*)d_in[1];
    const void*  msb  = d_in[2];
    const void*  lsb  = d_in[3];
    float*       out  = (float*)d_out;

    hist_kernel<<<K1_BLOCKS, K1_THREADS>>>(x_in, x_s);
    reduce_final_kernel<<<K2_BLOCKS, K2_THREADS>>>(msb, lsb, out);
}